// round 12
// baseline (speedup 1.0000x reference)
#include <cuda_runtime.h>
#include <cstdint>

// Problem constants
#define Bx    8
#define Cx    256
#define Kx    19
#define HW4   4096          // HW/4 (float4 units), HW = 128*128
#define RC    4             // c-rows per c-warp
#define CG    16            // c-rows per block
#define NCG   (Cx/CG)       // 16
#define CH    32            // float4 columns per chunk
#define NCHT  (HW4/CH)      // 128 chunks total
#define Sx    7             // hw splits -> grid 896, ~3 waves @ 2 blk/SM
#define NBUF  4             // map cp.async ring depth (prefetch distance 3)

// Scratch: att quarter-partials [s][b][c][k][quarter(4)]
__device__ float g_att_part[Sx * Bx * Cx * Kx * 4];

// ---- cp.async helpers ------------------------------------------------------
__device__ __forceinline__ void cp_async16(uint32_t saddr, const void* gptr) {
    asm volatile("cp.async.cg.shared.global [%0], [%1], 16;\n" :: "r"(saddr), "l"(gptr));
}
__device__ __forceinline__ void cp_commit() {
    asm volatile("cp.async.commit_group;\n");
}
template <int N>
__device__ __forceinline__ void cp_wait() {
    asm volatile("cp.async.wait_group %0;\n" :: "n"(N));
}
__device__ __forceinline__ uint32_t smem_u32(const void* p) {
    return (uint32_t)__cvta_generic_to_shared(p);
}
// Packed dual-FMA: acc(f32x2) += a(f32x2) * b(f32x2)
__device__ __forceinline__ void ffma2(unsigned long long& acc,
                                      unsigned long long a, unsigned long long b) {
    asm("fma.rn.f32x2 %0, %1, %2, %0;" : "+l"(acc) : "l"(a), "l"(b));
}

// ---------------------------------------------------------------------------
// Kernel 1: att partials.
//   map:     4-deep cp.async smem ring (proven R10 structure).
//   feature: REGISTER prefetch at depth 2 — LDGs for chunk ch+2 issued at the
//            top of chunk ch's body, consumed two phases later (~2 chunk-times
//            + compute of cover vs ~2000cyc queued DRAM latency). This removes
//            feature's 24KB/blk-chunk from the smem crossbar, which R10's
//            numbers identified as the new binding wall (1176 cyc/phase ->
//            ~777 map-only).
//   k-split: warps 0-3 k=0..9, warps 4-7 k=10..18 over the same 16 c-rows.
// ---------------------------------------------------------------------------
__global__ __launch_bounds__(256, 2)
void k_att(const float* __restrict__ feat, const float* __restrict__ map) {
    __shared__ float4 smap[NBUF][Kx * CH];          // 4 x 9728 B = 38.9 KB

    const int bid  = blockIdx.x;
    const int s    = bid % Sx;
    const int cg   = (bid / Sx) % NCG;
    const int b    = bid / (Sx * NCG);
    const int tid  = threadIdx.x;
    const int w    = tid >> 5;
    const int lane = tid & 31;
    const int wc   = w & 3;                         // c-subgroup 0..3
    const int kg   = w >> 2;                        // k-group 0/1
    const int KOFF = kg * 10;
    const int KN   = kg ? 9 : 10;
    const int c0   = cg * CG + wc * RC;

    const int ch_beg = (s * NCHT) / Sx;             // 18/19-chunk ranges
    const int ch_end = ((s + 1) * NCHT) / Sx;

    const float4* __restrict__ f4 = (const float4*)feat;
    const float4* __restrict__ m4 = (const float4*)map;
    const float4* fbase = f4 + (size_t)(b * Cx + c0) * HW4;
    const float4* mbase = m4 + (size_t)(b * Kx) * HW4;

    unsigned long long acc2[10 * RC];
    #pragma unroll
    for (int i = 0; i < 10 * RC; i++) acc2[i] = 0ull;

    // map-chunk loader: 19*32 = 608 float4 by 256 threads (smem writes only)
    auto load_map_chunk = [&](int chunk) {
        const float4* src = mbase + chunk * CH;
        uint32_t sb = smem_u32(&smap[chunk & (NBUF - 1)][0]);
        #pragma unroll
        for (int j = 0; j < 2; j++) {
            int e = tid + j * 256;                  // e = k*CH + col
            cp_async16(sb + e * 16, src + (size_t)(e >> 5) * HW4 + (e & 31));
        }
        if (tid < Kx * CH - 512) {                  // last 96
            int e = tid + 512;
            cp_async16(sb + e * 16, src + (size_t)(e >> 5) * HW4 + (e & 31));
        }
    };

    // Prologue: 3 map groups in flight; feature chunks ch_beg, ch_beg+1 in regs.
    #pragma unroll
    for (int p = 0; p < NBUF - 1; p++) {
        if (ch_beg + p < ch_end) load_map_chunk(ch_beg + p);
        cp_commit();
    }

    ulonglong2 fc[RC], fn[RC], fnn[RC];
    {
        const int col0 = ch_beg * CH + lane;
        #pragma unroll
        for (int c = 0; c < RC; c++)
            fc[c] = *(const ulonglong2*)(fbase + (size_t)c * HW4 + col0);
        const int col1 = col0 + CH;                 // ch_beg+1 (>=18 chunks, safe)
        #pragma unroll
        for (int c = 0; c < RC; c++)
            fn[c] = *(const ulonglong2*)(fbase + (size_t)c * HW4 + col1);
    }

    #pragma unroll 1
    for (int ch = ch_beg; ch < ch_end; ch++) {
        // Depth-2 feature prefetch: chunk ch+2, consumed two phases from now.
        if (ch + 2 < ch_end) {
            const int col = (ch + 2) * CH + lane;
            #pragma unroll
            for (int c = 0; c < RC; c++)
                fnn[c] = *(const ulonglong2*)(fbase + (size_t)c * HW4 + col);
        }

        cp_wait<NBUF - 2>();                        // chunk ch's map resident
        __syncthreads();                            // all warps done with ch-1

        if (ch + NBUF - 1 < ch_end) load_map_chunk(ch + NBUF - 1);
        cp_commit();                                // commit even if empty

        const float4* sb = smap[ch & (NBUF - 1)];
        #pragma unroll
        for (int j = 0; j < 10; j++) {
            if (j < KN) {
                ulonglong2 mv = *(const ulonglong2*)(&sb[(KOFF + j) * CH + lane]);
                #pragma unroll
                for (int c = 0; c < RC; c++)
                    ffma2(acc2[j * RC + c], fc[c].x, mv.x);
                #pragma unroll
                for (int c = 0; c < RC; c++)
                    ffma2(acc2[j * RC + c], fc[c].y, mv.y);
            }
        }
        #pragma unroll
        for (int c = 0; c < RC; c++) { fc[c] = fn[c]; fn[c] = fnn[c]; }
    }

    // Collapse packed pairs; 3-round lane reduction -> quarter partials.
    #pragma unroll
    for (int j = 0; j < 10; j++) {
        if (j < KN) {
            #pragma unroll
            for (int c = 0; c < RC; c++) {
                unsigned long long a = acc2[j * RC + c];
                float v = __uint_as_float((uint32_t)a)
                        + __uint_as_float((uint32_t)(a >> 32));
                v += __shfl_down_sync(0xffffffffu, v, 16);
                v += __shfl_down_sync(0xffffffffu, v, 8);
                v += __shfl_down_sync(0xffffffffu, v, 4);
                acc2[j * RC + c] = (unsigned long long)__float_as_uint(v);
            }
        }
    }
    if (lane < 4) {
        #pragma unroll
        for (int j = 0; j < 10; j++) {
            if (j < KN) {
                #pragma unroll
                for (int c = 0; c < RC; c++) {
                    float v = __uint_as_float((uint32_t)acc2[j * RC + c]);
                    g_att_part[((((size_t)s * Bx + b) * Cx + (c0 + c)) * Kx
                                + (KOFF + j)) * 4 + lane] = v;
                }
            }
        }
    }
}

// ---------------------------------------------------------------------------
// Kernel 2 (fused scale+apply): plain loads/stores (policy hints measured
// neutral-to-negative in R5/R8). Stable at ~39.3us / 70% DRAM.
// ---------------------------------------------------------------------------
__global__ __launch_bounds__(256)
void k_apply(const float* __restrict__ feat, const float* __restrict__ gamma,
             float* __restrict__ out) {
    __shared__ float sh[Kx + 1];
    const int row = blockIdx.x;                     // b*Cx + c
    const int tid = threadIdx.x;

    if (tid < Kx) {
        const float* p = g_att_part + (size_t)row * Kx * 4 + tid * 4;
        float a = 0.f;
        #pragma unroll
        for (int s = 0; s < Sx; s++) {
            const float* ps = p + (size_t)s * Bx * Cx * Kx * 4;
            a += ps[0] + ps[1] + ps[2] + ps[3];
        }
        sh[tid] = gamma[tid] * (1.f / (1.f + __expf(-a)));
    }
    __syncthreads();
    if (tid == 0) {
        float sc = 0.f;
        #pragma unroll
        for (int k = 0; k < Kx; k++) sc += sh[k];
        sh[Kx] = 1.f + sc;
    }
    __syncthreads();
    const float s = sh[Kx];

    const float4* __restrict__ fr = (const float4*)feat + (size_t)row * HW4;
    float4* __restrict__ orow = (float4*)out + (size_t)row * HW4;
    #pragma unroll 4
    for (int i = tid; i < HW4; i += 256) {
        float4 f = fr[i];
        f.x *= s; f.y *= s; f.z *= s; f.w *= s;
        orow[i] = f;
    }
}

// ---------------------------------------------------------------------------
extern "C" void kernel_launch(void* const* d_in, const int* in_sizes, int n_in,
                              void* d_out, int out_size) {
    const float* feat  = (const float*)d_in[0];
    const float* map_  = (const float*)d_in[1];
    const float* gamma = (const float*)d_in[2];
    float* out = (float*)d_out;

    k_att  <<<Bx * NCG * Sx, 256>>>(feat, map_);
    k_apply<<<Bx * Cx, 256>>>(feat, gamma, out);
}

// round 13
// speedup vs baseline: 1.0697x; 1.0697x over previous
#include <cuda_runtime.h>
#include <cstdint>

// Problem constants
#define Bx    8
#define Cx    256
#define Kx    19
#define HW4   4096          // HW/4 (float4 units), HW = 128*128
#define RC    4             // c-rows per c-warp
#define CG    16            // c-rows per block
#define NCG   (Cx/CG)       // 16
#define CH    64            // float4 columns per chunk (doubled vs R10)
#define NCHT  (HW4/CH)      // 64 chunks total
#define Sx    7             // hw splits -> grid 896, ~3 waves @ 2 blk/SM
#define NBUF  3             // cp.async ring depth (prefetch distance 2)

#define MAPV  (Kx*CH)       // 1216 float4 per map chunk
#define FEATV (CG*CH)       // 1024 float4 per feature chunk
#define BUFV  (MAPV+FEATV)  // 2240 float4 per ring buffer
#define SMEM_DYN (NBUF * BUFV * 16)   // 107520 B

// Scratch: att quarter-partials [s][b][c][k][quarter(4)]
__device__ float g_att_part[Sx * Bx * Cx * Kx * 4];

// ---- cp.async helpers ------------------------------------------------------
__device__ __forceinline__ void cp_async16(uint32_t saddr, const void* gptr) {
    asm volatile("cp.async.cg.shared.global [%0], [%1], 16;\n" :: "r"(saddr), "l"(gptr));
}
__device__ __forceinline__ void cp_commit() {
    asm volatile("cp.async.commit_group;\n");
}
template <int N>
__device__ __forceinline__ void cp_wait() {
    asm volatile("cp.async.wait_group %0;\n" :: "n"(N));
}
__device__ __forceinline__ uint32_t smem_u32(const void* p) {
    return (uint32_t)__cvta_generic_to_shared(p);
}
// Packed dual-FMA: acc(f32x2) += a(f32x2) * b(f32x2)
__device__ __forceinline__ void ffma2(unsigned long long& acc,
                                      unsigned long long a, unsigned long long b) {
    asm("fma.rn.f32x2 %0, %1, %2, %0;" : "+l"(acc) : "l"(a), "l"(b));
}

// ---------------------------------------------------------------------------
// Kernel 1: att partials — R10 structure (both tiles staged through the
// cp.async smem ring; that design measured 92.7us total) with CH doubled to
// 64 columns per chunk. Halves the phase count -> halves per-phase overhead
// (cp_wait + barrier + exposure), at constant total crossbar/LDGSTS/FFMA2
// work. Body processes the chunk as TWO 32-col halves so live register state
// stays at acc(80)+fc(16): the R11 lesson is that any extra multi-chunk
// register state spills under the 124-reg/2-block cap.
// k-split: warps 0-3 k=0..9, warps 4-7 k=10..18 over the same 16 c-rows.
// ---------------------------------------------------------------------------
__global__ __launch_bounds__(256, 2)
void k_att(const float* __restrict__ feat, const float* __restrict__ map) {
    extern __shared__ float4 dsm[];                 // [NBUF][MAPV + FEATV]

    const int bid  = blockIdx.x;
    const int s    = bid % Sx;
    const int cg   = (bid / Sx) % NCG;
    const int b    = bid / (Sx * NCG);
    const int tid  = threadIdx.x;
    const int w    = tid >> 5;
    const int lane = tid & 31;
    const int wc   = w & 3;                         // c-subgroup 0..3
    const int kg   = w >> 2;                        // k-group 0/1
    const int KOFF = kg * 10;
    const int KN   = kg ? 9 : 10;
    const int c0   = cg * CG + wc * RC;

    const int ch_beg = (s * NCHT) / Sx;             // 9/10-chunk ranges
    const int ch_end = ((s + 1) * NCHT) / Sx;

    const float4* __restrict__ f4 = (const float4*)feat;
    const float4* __restrict__ m4 = (const float4*)map;
    const float4* fblk  = f4 + (size_t)(b * Cx + cg * CG) * HW4;
    const float4* mbase = m4 + (size_t)(b * Kx) * HW4;

    unsigned long long acc2[10 * RC];
    #pragma unroll
    for (int i = 0; i < 10 * RC; i++) acc2[i] = 0ull;

    // one group = map chunk (1216 f4) + feature chunk (1024 f4), 256 threads
    auto load_chunk = [&](int chunk) {
        float4* bufm = dsm + (chunk % NBUF) * BUFV;
        float4* buff = bufm + MAPV;
        const float4* msrc = mbase + chunk * CH;
        const float4* fsrc = fblk + chunk * CH;
        uint32_t sbm = smem_u32(bufm);
        uint32_t sbf = smem_u32(buff);
        #pragma unroll
        for (int j = 0; j < 4; j++) {               // map 1024 of 1216
            int e = tid + j * 256;                  // e = k*CH + col
            cp_async16(sbm + e * 16, msrc + (size_t)(e >> 6) * HW4 + (e & 63));
        }
        if (tid < MAPV - 1024) {                    // map last 192
            int e = tid + 1024;
            cp_async16(sbm + e * 16, msrc + (size_t)(e >> 6) * HW4 + (e & 63));
        }
        #pragma unroll
        for (int j = 0; j < 4; j++) {               // feature 1024
            int e = tid + j * 256;                  // e = row*CH + col
            cp_async16(sbf + e * 16, fsrc + (size_t)(e >> 6) * HW4 + (e & 63));
        }
    };

    #pragma unroll
    for (int p = 0; p < NBUF - 1; p++) {
        if (ch_beg + p < ch_end) load_chunk(ch_beg + p);
        cp_commit();
    }

    #pragma unroll 1
    for (int ch = ch_beg; ch < ch_end; ch++) {
        cp_wait<NBUF - 2>();                        // chunk ch resident
        __syncthreads();                            // all warps done with ch-1

        if (ch + NBUF - 1 < ch_end) load_chunk(ch + NBUF - 1);
        cp_commit();                                // commit even if empty

        const float4* bufm = dsm + (ch % NBUF) * BUFV;
        const float4* buff = bufm + MAPV;

        // Two 32-column halves: fc live-range = one half (16 regs).
        #pragma unroll
        for (int h = 0; h < 2; h++) {
            const int colb = h * 32 + lane;
            ulonglong2 fc[RC];
            #pragma unroll
            for (int c = 0; c < RC; c++)
                fc[c] = *(const ulonglong2*)(&buff[(wc * RC + c) * CH + colb]);

            #pragma unroll
            for (int j = 0; j < 10; j++) {
                if (j < KN) {
                    ulonglong2 mv =
                        *(const ulonglong2*)(&bufm[(KOFF + j) * CH + colb]);
                    #pragma unroll
                    for (int c = 0; c < RC; c++)
                        ffma2(acc2[j * RC + c], fc[c].x, mv.x);
                    #pragma unroll
                    for (int c = 0; c < RC; c++)
                        ffma2(acc2[j * RC + c], fc[c].y, mv.y);
                }
            }
        }
    }

    // Collapse packed pairs; 3-round lane reduction -> quarter partials.
    #pragma unroll
    for (int j = 0; j < 10; j++) {
        if (j < KN) {
            #pragma unroll
            for (int c = 0; c < RC; c++) {
                unsigned long long a = acc2[j * RC + c];
                float v = __uint_as_float((uint32_t)a)
                        + __uint_as_float((uint32_t)(a >> 32));
                v += __shfl_down_sync(0xffffffffu, v, 16);
                v += __shfl_down_sync(0xffffffffu, v, 8);
                v += __shfl_down_sync(0xffffffffu, v, 4);
                acc2[j * RC + c] = (unsigned long long)__float_as_uint(v);
            }
        }
    }
    if (lane < 4) {
        #pragma unroll
        for (int j = 0; j < 10; j++) {
            if (j < KN) {
                #pragma unroll
                for (int c = 0; c < RC; c++) {
                    float v = __uint_as_float((uint32_t)acc2[j * RC + c]);
                    g_att_part[((((size_t)s * Bx + b) * Cx + (c0 + c)) * Kx
                                + (KOFF + j)) * 4 + lane] = v;
                }
            }
        }
    }
}

// ---------------------------------------------------------------------------
// Kernel 2 (fused scale+apply): stable at ~39.3us / 70% DRAM. Plain ld/st.
// ---------------------------------------------------------------------------
__global__ __launch_bounds__(256)
void k_apply(const float* __restrict__ feat, const float* __restrict__ gamma,
             float* __restrict__ out) {
    __shared__ float sh[Kx + 1];
    const int row = blockIdx.x;                     // b*Cx + c
    const int tid = threadIdx.x;

    if (tid < Kx) {
        const float* p = g_att_part + (size_t)row * Kx * 4 + tid * 4;
        float a = 0.f;
        #pragma unroll
        for (int s = 0; s < Sx; s++) {
            const float* ps = p + (size_t)s * Bx * Cx * Kx * 4;
            a += ps[0] + ps[1] + ps[2] + ps[3];
        }
        sh[tid] = gamma[tid] * (1.f / (1.f + __expf(-a)));
    }
    __syncthreads();
    if (tid == 0) {
        float sc = 0.f;
        #pragma unroll
        for (int k = 0; k < Kx; k++) sc += sh[k];
        sh[Kx] = 1.f + sc;
    }
    __syncthreads();
    const float s = sh[Kx];

    const float4* __restrict__ fr = (const float4*)feat + (size_t)row * HW4;
    float4* __restrict__ orow = (float4*)out + (size_t)row * HW4;
    #pragma unroll 4
    for (int i = tid; i < HW4; i += 256) {
        float4 f = fr[i];
        f.x *= s; f.y *= s; f.z *= s; f.w *= s;
        orow[i] = f;
    }
}

// ---------------------------------------------------------------------------
extern "C" void kernel_launch(void* const* d_in, const int* in_sizes, int n_in,
                              void* d_out, int out_size) {
    const float* feat  = (const float*)d_in[0];
    const float* map_  = (const float*)d_in[1];
    const float* gamma = (const float*)d_in[2];
    float* out = (float*)d_out;

    cudaFuncSetAttribute(k_att, cudaFuncAttributeMaxDynamicSharedMemorySize,
                         SMEM_DYN);

    k_att  <<<Bx * NCG * Sx, 256, SMEM_DYN>>>(feat, map_);
    k_apply<<<Bx * Cx, 256>>>(feat, gamma, out);
}

// round 15
// speedup vs baseline: 1.2607x; 1.1785x over previous
#include <cuda_runtime.h>
#include <cstdint>

// Problem constants
#define Bx    8
#define Cx    256
#define Kx    19
#define HW4   4096          // HW/4 (float4 units), HW = 128*128
#define RC    4             // c-rows per c-warp
#define CG    16            // c-rows per block
#define NCG   (Cx/CG)       // 16
#define CH    64            // float4 columns per chunk
#define NCHT  (HW4/CH)      // 64 chunks total
#define Sx    7             // hw splits -> grid 896, ~3 waves @ 2 blk/SM
#define MBUF  3             // map ring depth
#define FBUF  2             // feature ring depth

#define MAPV  (Kx*CH)       // 1216 float4 per map chunk
#define FEATV (CG*CH)       // 1024 float4 per feature chunk
// smem: 3*1216*16 + 2*1024*16 = 91136 B  (2 blocks/SM fits)
#define SMEM_DYN (MBUF*MAPV*16 + FBUF*FEATV*16)

// Scratch: att quarter-partials [s][b][c][k][quarter(4)]
__device__ float g_att_part[Sx * Bx * Cx * Kx * 4];

// ---- cp.async helpers ------------------------------------------------------
__device__ __forceinline__ void cp_async16(uint32_t saddr, const void* gptr) {
    asm volatile("cp.async.cg.shared.global [%0], [%1], 16;\n" :: "r"(saddr), "l"(gptr));
}
__device__ __forceinline__ void cp_commit() {
    asm volatile("cp.async.commit_group;\n");
}
template <int N>
__device__ __forceinline__ void cp_wait() {
    asm volatile("cp.async.wait_group %0;\n" :: "n"(N));
}
__device__ __forceinline__ uint32_t smem_u32(const void* p) {
    return (uint32_t)__cvta_generic_to_shared(p);
}
// Packed dual-FMA: acc(f32x2) += a(f32x2) * b(f32x2)
__device__ __forceinline__ void ffma2(unsigned long long& acc,
                                      unsigned long long a, unsigned long long b) {
    asm("fma.rn.f32x2 %0, %1, %2, %0;" : "+l"(acc) : "l"(a), "l"(b));
}

// ---------------------------------------------------------------------------
// Kernel 1: att partials. CH=64 (half the phases of R10), split smem rings.
//
// cp.async GROUP DISCIPLINE (the R13 bug): wait_group<1> only guarantees all
// but the NEWEST group. So the feature group must never be newest at a wait.
// Two groups per iter, feature first:
//   prologue: G1={feat(b), map(b)}; G2={map(b+1)}
//   iter ch : cp_wait<1>  -> complete: ... Gf(ch-1)={feat(ch)}, Gm(ch-2)={map(ch)}
//             (only Gm(ch-1)={map(ch+1)} may still fly)
//             __syncthreads -> commit Gf(ch)={feat(ch+1)}; commit Gm(ch)={map(ch+2)}
// Overwrite safety: writes target feat[(ch+1)%2]=[(ch-1)%2] and
// map[(ch+2)%3]=[(ch-1)%3], both dead after this iter's barrier.
// k-split: warps 0-3 k=0..9, warps 4-7 k=10..18 over the same 16 c-rows.
// Register budget: acc 80 + <=20 transient (anything more spills: R11).
// ---------------------------------------------------------------------------
__global__ __launch_bounds__(256, 2)
void k_att(const float* __restrict__ feat, const float* __restrict__ map) {
    extern __shared__ float4 dsm[];                 // [MBUF*MAPV | FBUF*FEATV]
    float4* const mring = dsm;
    float4* const fring = dsm + MBUF * MAPV;

    const int bid  = blockIdx.x;
    const int s    = bid % Sx;
    const int cg   = (bid / Sx) % NCG;
    const int b    = bid / (Sx * NCG);
    const int tid  = threadIdx.x;
    const int w    = tid >> 5;
    const int lane = tid & 31;
    const int wc   = w & 3;                         // c-subgroup 0..3
    const int kg   = w >> 2;                        // k-group 0/1
    const int KOFF = kg * 10;
    const int KN   = kg ? 9 : 10;
    const int c0   = cg * CG + wc * RC;

    const int ch_beg = (s * NCHT) / Sx;             // 9/10-chunk ranges
    const int ch_end = ((s + 1) * NCHT) / Sx;

    const float4* __restrict__ f4 = (const float4*)feat;
    const float4* __restrict__ m4 = (const float4*)map;
    const float4* fblk  = f4 + (size_t)(b * Cx + cg * CG) * HW4;
    const float4* mbase = m4 + (size_t)(b * Kx) * HW4;

    unsigned long long acc2[10 * RC];
    #pragma unroll
    for (int i = 0; i < 10 * RC; i++) acc2[i] = 0ull;

    // map chunk: 1216 float4 by 256 threads
    auto load_map = [&](int chunk) {
        const float4* src = mbase + chunk * CH;
        uint32_t sb = smem_u32(mring + (chunk % MBUF) * MAPV);
        #pragma unroll
        for (int j = 0; j < 4; j++) {               // 1024
            int e = tid + j * 256;                  // e = k*64 + col
            cp_async16(sb + e * 16, src + (size_t)(e >> 6) * HW4 + (e & 63));
        }
        if (tid < MAPV - 1024) {                    // last 192
            int e = tid + 1024;
            cp_async16(sb + e * 16, src + (size_t)(e >> 6) * HW4 + (e & 63));
        }
    };
    // feature chunk: 1024 float4 by 256 threads
    auto load_feat = [&](int chunk) {
        const float4* src = fblk + chunk * CH;
        uint32_t sb = smem_u32(fring + (chunk % FBUF) * FEATV);
        #pragma unroll
        for (int j = 0; j < 4; j++) {
            int e = tid + j * 256;                  // e = row*64 + col
            cp_async16(sb + e * 16, src + (size_t)(e >> 6) * HW4 + (e & 63));
        }
    };

    // Prologue: G1 = {feat(b), map(b)}; G2 = {map(b+1)} (never leaves feat newest)
    load_feat(ch_beg);
    load_map(ch_beg);
    cp_commit();                                    // G1
    load_map(ch_beg + 1);                           // >=9 chunks per split: safe
    cp_commit();                                    // G2

    #pragma unroll 1
    for (int ch = ch_beg; ch < ch_end; ch++) {
        cp_wait<1>();                               // feat(ch) + map(ch) complete
        __syncthreads();                            // all warps done with ch-1

        if (ch + 1 < ch_end) load_feat(ch + 1);
        cp_commit();                                // Gf(ch) (empty ok)
        if (ch + 2 < ch_end) load_map(ch + 2);
        cp_commit();                                // Gm(ch) (empty ok)

        const float4* bufm = mring + (ch % MBUF) * MAPV;
        const float4* buff = fring + (ch % FBUF) * FEATV;

        // Two 32-column halves keep live registers at acc(80)+fc(16).
        #pragma unroll
        for (int h = 0; h < 2; h++) {
            const int colb = h * 32 + lane;
            ulonglong2 fc[RC];
            #pragma unroll
            for (int c = 0; c < RC; c++)
                fc[c] = *(const ulonglong2*)(&buff[(wc * RC + c) * CH + colb]);

            #pragma unroll
            for (int j = 0; j < 10; j++) {
                if (j < KN) {
                    ulonglong2 mv =
                        *(const ulonglong2*)(&bufm[(KOFF + j) * CH + colb]);
                    #pragma unroll
                    for (int c = 0; c < RC; c++)
                        ffma2(acc2[j * RC + c], fc[c].x, mv.x);
                    #pragma unroll
                    for (int c = 0; c < RC; c++)
                        ffma2(acc2[j * RC + c], fc[c].y, mv.y);
                }
            }
        }
    }

    // Collapse packed pairs; 3-round lane reduction -> quarter partials.
    #pragma unroll
    for (int j = 0; j < 10; j++) {
        if (j < KN) {
            #pragma unroll
            for (int c = 0; c < RC; c++) {
                unsigned long long a = acc2[j * RC + c];
                float v = __uint_as_float((uint32_t)a)
                        + __uint_as_float((uint32_t)(a >> 32));
                v += __shfl_down_sync(0xffffffffu, v, 16);
                v += __shfl_down_sync(0xffffffffu, v, 8);
                v += __shfl_down_sync(0xffffffffu, v, 4);
                acc2[j * RC + c] = (unsigned long long)__float_as_uint(v);
            }
        }
    }
    if (lane < 4) {
        #pragma unroll
        for (int j = 0; j < 10; j++) {
            if (j < KN) {
                #pragma unroll
                for (int c = 0; c < RC; c++) {
                    float v = __uint_as_float((uint32_t)acc2[j * RC + c]);
                    g_att_part[((((size_t)s * Bx + b) * Cx + (c0 + c)) * Kx
                                + (KOFF + j)) * 4 + lane] = v;
                }
            }
        }
    }
}

// ---------------------------------------------------------------------------
// Kernel 2 (fused scale+apply): stable ~39.3us / 70% DRAM. Plain ld/st.
// ---------------------------------------------------------------------------
__global__ __launch_bounds__(256)
void k_apply(const float* __restrict__ feat, const float* __restrict__ gamma,
             float* __restrict__ out) {
    __shared__ float sh[Kx + 1];
    const int row = blockIdx.x;                     // b*Cx + c
    const int tid = threadIdx.x;

    if (tid < Kx) {
        const float* p = g_att_part + (size_t)row * Kx * 4 + tid * 4;
        float a = 0.f;
        #pragma unroll
        for (int s = 0; s < Sx; s++) {
            const float* ps = p + (size_t)s * Bx * Cx * Kx * 4;
            a += ps[0] + ps[1] + ps[2] + ps[3];
        }
        sh[tid] = gamma[tid] * (1.f / (1.f + __expf(-a)));
    }
    __syncthreads();
    if (tid == 0) {
        float sc = 0.f;
        #pragma unroll
        for (int k = 0; k < Kx; k++) sc += sh[k];
        sh[Kx] = 1.f + sc;
    }
    __syncthreads();
    const float s = sh[Kx];

    const float4* __restrict__ fr = (const float4*)feat + (size_t)row * HW4;
    float4* __restrict__ orow = (float4*)out + (size_t)row * HW4;
    #pragma unroll 4
    for (int i = tid; i < HW4; i += 256) {
        float4 f = fr[i];
        f.x *= s; f.y *= s; f.z *= s; f.w *= s;
        orow[i] = f;
    }
}

// ---------------------------------------------------------------------------
extern "C" void kernel_launch(void* const* d_in, const int* in_sizes, int n_in,
                              void* d_out, int out_size) {
    const float* feat  = (const float*)d_in[0];
    const float* map_  = (const float*)d_in[1];
    const float* gamma = (const float*)d_in[2];
    float* out = (float*)d_out;

    cudaFuncSetAttribute(k_att, cudaFuncAttributeMaxDynamicSharedMemorySize,
                         SMEM_DYN);

    k_att  <<<Bx * NCG * Sx, 256, SMEM_DYN>>>(feat, map_);
    k_apply<<<Bx * Cx, 256>>>(feat, gamma, out);
}